// round 9
// baseline (speedup 1.0000x reference)
#include <cuda_runtime.h>
#include <math.h>

// ---------------- problem constants ----------------
constexpr int kB    = 16;
constexpr int kL    = 64;
constexpr int kD    = 256;
constexpr int kDIN  = 512;
constexpr int kH    = 8;
constexpr int kDH   = 64;
constexpr int kN    = 64;
constexpr int kCDIM = 640;
constexpr int kP    = 1160;
constexpr int kPF   = 768;
constexpr int kCLS  = 1000;
constexpr float kEPS = 1e-6f;
constexpr int kTOK  = kB * kL;  // 1024

// GEMM smem geometry (floats)
constexpr int kAStride = 36;
constexpr int kBStride = 72;
constexpr int kBStage  = 32 * kBStride;      // 2304

// attn kernel smem layout (floats) — all strides float4-friendly
constexpr int aW   = 0;          // 64*68 (raw staging, then W)
constexpr int aX   = 4352;       // 64*68
constexpr int aBT  = 8704;       // 64*68  (B transposed: [n][s'])
constexpr int aC   = 13056;      // 64*66
constexpr int aDT  = 17280;      // 64
constexpr int aCUM = 17344;      // 64
constexpr int kAttnSmemBytes = 17408 * 4;    // 69632

// ---------------- scratch ----------------
__device__ float g_t[kTOK*kD];
__device__ float g_nx[kTOK*kD];
__device__ float g_zx[2][kTOK*kP];
__device__ float g_y[2][kTOK*kDIN];
__device__ float g_o[2][kTOK*kD];

// ---------------- helpers ----------------
__device__ __forceinline__ int snake_src(int l) {
    int r = l >> 3, c = l & 7;
    return r * 8 + ((r & 1) ? (7 - c) : c);
}

__device__ __forceinline__ float block_reduce_sum_256(float v) {
    __shared__ float sh[8];
    __shared__ float tot;
    int lane = threadIdx.x & 31, w = threadIdx.x >> 5;
    #pragma unroll
    for (int o = 16; o > 0; o >>= 1) v += __shfl_xor_sync(0xffffffffu, v, o);
    if (lane == 0) sh[w] = v;
    __syncthreads();
    if (w == 0) {
        float x = (lane < 8) ? sh[lane] : 0.f;
        #pragma unroll
        for (int o = 4; o > 0; o >>= 1) x += __shfl_xor_sync(0xffffffffu, x, o);
        if (lane == 0) tot = x;
    }
    __syncthreads();
    return tot;
}

__device__ __forceinline__ float siluf(float x) {
    return x / (1.f + expf(-x));
}

__device__ __forceinline__ unsigned f2tf32(float f) {
    unsigned r;
    asm("cvt.rna.tf32.f32 %0, %1;" : "=r"(r) : "f"(f));
    return r;
}

__device__ __forceinline__ void cpa16(float* dst, const float* src) {
    unsigned d = (unsigned)__cvta_generic_to_shared(dst);
    asm volatile("cp.async.cg.shared.global [%0], [%1], 16;" :: "r"(d), "l"(src));
}

// ---------------- kernels ----------------

// ---- patch GEMM: 64x64 tiles (fused patchify + transpose-B + bias + pos) ----
__global__ void __launch_bounds__(256) k_gemm_patch(
        const float* __restrict__ x, const float* __restrict__ Bw,
        const float* __restrict__ pb, const float* __restrict__ pos,
        float* __restrict__ C) {
    __shared__ unsigned As[16][72];
    __shared__ unsigned Bs[16][72];
    int tid = threadIdx.x;
    int lane = tid & 31, warp = tid >> 5;
    int lg = lane >> 2, lt = lane & 3;
    int wm = (warp >> 2) * 32;
    int wn = (warp & 3) * 16;
    int m0 = blockIdx.y * 64, n0 = blockIdx.x * 64;

    float c[2][2][4];
    #pragma unroll
    for (int a = 0; a < 2; a++)
        #pragma unroll
        for (int b = 0; b < 2; b++)
            #pragma unroll
            for (int d = 0; d < 4; d++) c[a][b][d] = 0.f;

    int am = tid >> 2;
    int ak = (tid & 3) * 4;
    int bk = tid >> 4;
    int bn = (tid & 15) * 4;

    int m = m0 + am;
    int bimg = m >> 6, l = m & 63;
    int src = snake_src(l);
    int gr = src >> 3, gc = src & 7;

    for (int k0 = 0; k0 < kPF; k0 += 16) {
        {
            int f = k0 + ak;
            int ch = f >> 8, rem = f & 255;
            int pr = rem >> 4, pc = rem & 15;
            const float* ap = x + ((long)(bimg * 3 + ch) * 128 + gr * 16 + pr) * 128
                                + gc * 16 + pc;
            float4 v = *(const float4*)(ap);
            As[ak + 0][am] = f2tf32(v.x);
            As[ak + 1][am] = f2tf32(v.y);
            As[ak + 2][am] = f2tf32(v.z);
            As[ak + 3][am] = f2tf32(v.w);
        }
        {
            #pragma unroll
            for (int j = 0; j < 4; j++)
                Bs[bk][bn + j] = f2tf32(Bw[(long)(n0 + bn + j) * kPF + k0 + bk]);
        }
        __syncthreads();
        #pragma unroll
        for (int k8 = 0; k8 < 16; k8 += 8) {
            unsigned afr[2][4], bfr[2][2];
            #pragma unroll
            for (int mt = 0; mt < 2; mt++) {
                int mb = wm + mt * 16;
                afr[mt][0] = As[k8 + lt][mb + lg];
                afr[mt][1] = As[k8 + lt][mb + 8 + lg];
                afr[mt][2] = As[k8 + lt + 4][mb + lg];
                afr[mt][3] = As[k8 + lt + 4][mb + 8 + lg];
            }
            #pragma unroll
            for (int nt = 0; nt < 2; nt++) {
                bfr[nt][0] = Bs[k8 + lt][wn + nt * 8 + lg];
                bfr[nt][1] = Bs[k8 + lt + 4][wn + nt * 8 + lg];
            }
            #pragma unroll
            for (int mt = 0; mt < 2; mt++)
                #pragma unroll
                for (int nt = 0; nt < 2; nt++)
                    asm volatile(
                        "mma.sync.aligned.m16n8k8.row.col.f32.tf32.tf32.f32 "
                        "{%0,%1,%2,%3}, {%4,%5,%6,%7}, {%8,%9}, {%0,%1,%2,%3};"
                        : "+f"(c[mt][nt][0]), "+f"(c[mt][nt][1]),
                          "+f"(c[mt][nt][2]), "+f"(c[mt][nt][3])
                        : "r"(afr[mt][0]), "r"(afr[mt][1]),
                          "r"(afr[mt][2]), "r"(afr[mt][3]),
                          "r"(bfr[nt][0]), "r"(bfr[nt][1]));
        }
        __syncthreads();
    }

    #pragma unroll
    for (int mt = 0; mt < 2; mt++) {
        int r0 = m0 + wm + mt * 16 + lg;
        int l0 = r0 & 63, l8 = (r0 + 8) & 63;
        int s0 = snake_src(l0) * kD, s8 = snake_src(l8) * kD;
        #pragma unroll
        for (int nt = 0; nt < 2; nt++) {
            int gn = n0 + wn + nt * 8 + 2 * lt;
            C[(long)r0 * kD + gn]           = c[mt][nt][0] + pb[gn] + pos[s0 + gn];
            C[(long)r0 * kD + gn + 1]       = c[mt][nt][1] + pb[gn + 1] + pos[s0 + gn + 1];
            C[(long)(r0 + 8) * kD + gn]     = c[mt][nt][2] + pb[gn] + pos[s8 + gn];
            C[(long)(r0 + 8) * kD + gn + 1] = c[mt][nt][3] + pb[gn + 1] + pos[s8 + gn + 1];
        }
    }
}

// ---- TF32 GEMM, cp.async double-buffered, K-step 32, templated M-tile ----
template<int MT>
__global__ void __launch_bounds__(256) k_gemm_tc(
        const float* __restrict__ Abase,
        const float* __restrict__ B0, const float* __restrict__ B1,
        float* __restrict__ Cbase,
        int M, int N, int K, long sA, long sC) {
    extern __shared__ float smem[];
    constexpr int NTF = (MT == 128) ? 4 : 2;
    constexpr int ASTAGE = MT * kAStride;
    constexpr int BBASE = 2 * ASTAGE;
    int z = blockIdx.z;
    const float* A = Abase + (long)z * sA;
    const float* B = z ? B1 : B0;
    float* C = Cbase + (long)z * sC;
    int tid = threadIdx.x;
    int lane = tid & 31, warp = tid >> 5;
    int lg = lane >> 2, lt = lane & 3;
    int wm = (MT == 128) ? (warp >> 1) * 32 : (warp >> 2) * 32;
    int wn = (MT == 128) ? (warp & 1) * 32 : (warp & 3) * 16;
    int m0 = blockIdx.y * MT, n0 = blockIdx.x * 64;

    float c[2][NTF][4];
    #pragma unroll
    for (int a = 0; a < 2; a++)
        #pragma unroll
        for (int b = 0; b < NTF; b++)
            #pragma unroll
            for (int d = 0; d < 4; d++) c[a][b][d] = 0.f;

    int am = (MT == 128) ? (tid >> 1) : (tid >> 2);
    int ak = (MT == 128) ? (tid & 1) * 16 : (tid & 3) * 8;
    int bk = tid >> 3, bn = (tid & 7) * 8;

    if (n0 + 64 > N) {
        for (int i = tid; i < 2 * kBStage; i += 256) smem[BBASE + i] = 0.f;
        __syncthreads();
    }

    int nIters = K >> 5;

    {
        const float* ap = A + (long)(m0 + am) * K + ak;
        float* ad = &smem[am * kAStride + ak];
        cpa16(ad, ap); cpa16(ad + 4, ap + 4);
        if (MT == 128) { cpa16(ad + 8, ap + 8); cpa16(ad + 12, ap + 12); }
        const float* bp = B + (long)bk * N + n0 + bn;
        float* bd = &smem[BBASE + bk * kBStride + bn];
        if (n0 + bn < N) cpa16(bd, bp);
        if (n0 + bn + 4 < N) cpa16(bd + 4, bp + 4);
        asm volatile("cp.async.commit_group;");
    }

    for (int it = 0; it < nIters; it++) {
        if (it + 1 < nIters) {
            int k0 = (it + 1) << 5;
            int st = (it + 1) & 1;
            const float* ap = A + (long)(m0 + am) * K + k0 + ak;
            float* ad = &smem[st * ASTAGE + am * kAStride + ak];
            cpa16(ad, ap); cpa16(ad + 4, ap + 4);
            if (MT == 128) { cpa16(ad + 8, ap + 8); cpa16(ad + 12, ap + 12); }
            const float* bp = B + (long)(k0 + bk) * N + n0 + bn;
            float* bd = &smem[BBASE + st * kBStage + bk * kBStride + bn];
            if (n0 + bn < N) cpa16(bd, bp);
            if (n0 + bn + 4 < N) cpa16(bd + 4, bp + 4);
            asm volatile("cp.async.commit_group;");
            asm volatile("cp.async.wait_group 1;");
        } else {
            asm volatile("cp.async.wait_group 0;");
        }
        __syncthreads();

        const float* Ab = &smem[(it & 1) * ASTAGE];
        const float* Bb = &smem[BBASE + (it & 1) * kBStage];
        #pragma unroll
        for (int k8 = 0; k8 < 32; k8 += 8) {
            unsigned afr[2][4], bfr[NTF][2];
            #pragma unroll
            for (int mt = 0; mt < 2; mt++) {
                int mb = wm + mt * 16;
                afr[mt][0] = f2tf32(Ab[(mb + lg) * kAStride + k8 + lt]);
                afr[mt][1] = f2tf32(Ab[(mb + 8 + lg) * kAStride + k8 + lt]);
                afr[mt][2] = f2tf32(Ab[(mb + lg) * kAStride + k8 + lt + 4]);
                afr[mt][3] = f2tf32(Ab[(mb + 8 + lg) * kAStride + k8 + lt + 4]);
            }
            #pragma unroll
            for (int nt = 0; nt < NTF; nt++) {
                bfr[nt][0] = f2tf32(Bb[(k8 + lt) * kBStride + wn + nt * 8 + lg]);
                bfr[nt][1] = f2tf32(Bb[(k8 + lt + 4) * kBStride + wn + nt * 8 + lg]);
            }
            #pragma unroll
            for (int mt = 0; mt < 2; mt++)
                #pragma unroll
                for (int nt = 0; nt < NTF; nt++)
                    asm volatile(
                        "mma.sync.aligned.m16n8k8.row.col.f32.tf32.tf32.f32 "
                        "{%0,%1,%2,%3}, {%4,%5,%6,%7}, {%8,%9}, {%0,%1,%2,%3};"
                        : "+f"(c[mt][nt][0]), "+f"(c[mt][nt][1]),
                          "+f"(c[mt][nt][2]), "+f"(c[mt][nt][3])
                        : "r"(afr[mt][0]), "r"(afr[mt][1]),
                          "r"(afr[mt][2]), "r"(afr[mt][3]),
                          "r"(bfr[nt][0]), "r"(bfr[nt][1]));
        }
        __syncthreads();
    }

    #pragma unroll
    for (int mt = 0; mt < 2; mt++) {
        int r0 = m0 + wm + mt * 16 + lg;
        #pragma unroll
        for (int nt = 0; nt < NTF; nt++) {
            int gn = n0 + wn + nt * 8 + 2 * lt;
            if (gn < N) {
                C[(long)r0 * N + gn] = c[mt][nt][0];
                C[(long)(r0 + 8) * N + gn] = c[mt][nt][2];
                if (gn + 1 < N) {
                    C[(long)r0 * N + gn + 1] = c[mt][nt][1];
                    C[(long)(r0 + 8) * N + gn + 1] = c[mt][nt][3];
                }
            }
        }
    }
}

// ---- fused residual + rmsnorm ----
__global__ void k_resnorm(float* __restrict__ t, const float* __restrict__ o0,
                          const float* __restrict__ o1, const float* __restrict__ w,
                          float* __restrict__ nx, int addRes) {
    int row = blockIdx.x;
    int d = threadIdx.x;
    long i = (long)row * kD + d;
    float v = t[i];
    if (addRes) {
        v += 0.5f * (o0[i] + o1[i]);
        t[i] = v;
    }
    float ss = block_reduce_sum_256(v * v);
    nx[i] = v * rsqrtf(ss * (1.f / kD) + kEPS) * w[d];
}

// ---- chunked dual-form "scan": conv + dt + decay-masked attention ----
// grid (kB, kH, 2), 1024 threads.
__global__ void __launch_bounds__(1024) k_attn(
        const float* __restrict__ zxbase,
        const float* __restrict__ cw0, const float* __restrict__ cw1,
        const float* __restrict__ cb0, const float* __restrict__ cb1,
        const float* __restrict__ dtb0, const float* __restrict__ dtb1,
        const float* __restrict__ Alog0, const float* __restrict__ Alog1,
        const float* __restrict__ Dp0, const float* __restrict__ Dp1,
        float* __restrict__ ybase) {
    extern __shared__ float sm[];
    int b = blockIdx.x, h = blockIdx.y, dir = blockIdx.z;
    const float* zx = zxbase + (long)dir * kTOK * kP;
    float* y        = ybase  + (long)dir * kTOK * kDIN;
    const float* cw  = dir ? cw1 : cw0;
    const float* cb  = dir ? cb1 : cb0;
    float a = -expf((dir ? Alog1 : Alog0)[h]);
    float dpar = (dir ? Dp1 : Dp0)[h];
    float dtbv = (dir ? dtb1 : dtb0)[h];
    int tid = threadIdx.x;
    int nthr = blockDim.x;   // 1024

    // ---- phase 0: conv + silu into sX [s][p], sBT [n][s'], sC [s][n] ----
    #pragma unroll
    for (int seg = 0; seg < 3; seg++) {
        int off = (seg == 0) ? h * kDH : (seg == 1) ? kDIN : kDIN + kN;
        // stage raw via float4 (1024 quads)
        for (int idx = tid; idx < 1024; idx += nthr) {
            int s = idx >> 4, q = (idx & 15) * 4;
            int tok = dir ? (kL - 1 - s) : s;
            float4 v = *(const float4*)&zx[(long)(b * kL + tok) * kP + kDIN + off + q];
            *(float4*)&sm[aW + s * 68 + q] = v;
        }
        __syncthreads();
        if (seg == 1) {
            for (int idx = tid; idx < 4096; idx += nthr) {
                int s = idx & 63, cc = idx >> 6;
                float acc = cb[off + cc];
                #pragma unroll
                for (int k = 0; k < 4; k++) {
                    int sp = s - 3 + k;
                    if (sp >= 0) acc += cw[(off + cc) * 4 + k] * sm[aW + sp * 68 + cc];
                }
                sm[aBT + cc * 68 + s] = siluf(acc);
            }
        } else {
            int dst = (seg == 0) ? aX : aC;
            int stride = (seg == 0) ? 68 : 66;
            for (int idx = tid; idx < 4096; idx += nthr) {
                int s = idx >> 6, cc = idx & 63;
                float acc = cb[off + cc];
                #pragma unroll
                for (int k = 0; k < 4; k++) {
                    int sp = s - 3 + k;
                    if (sp >= 0) acc += cw[(off + cc) * 4 + k] * sm[aW + sp * 68 + cc];
                }
                sm[dst + s * stride + cc] = siluf(acc);
            }
        }
        __syncthreads();
    }

    // dt (softplus) + inclusive cumsum
    if (tid < 64) {
        int s = tid;
        int tok = dir ? (kL - 1 - s) : s;
        float v = zx[(long)(b * kL + tok) * kP + 2 * kDIN + 2 * kN + h] + dtbv;
        sm[aDT + s] = (v > 20.f) ? v : log1pf(expf(v));
    }
    __syncthreads();
    if (tid < 32) {
        float d0 = sm[aDT + 2 * tid], d1 = sm[aDT + 2 * tid + 1];
        float p = d0 + d1;
        #pragma unroll
        for (int o = 1; o < 32; o <<= 1) {
            float t = __shfl_up_sync(0xffffffffu, p, o);
            if (tid >= o) p += t;
        }
        sm[aCUM + 2 * tid] = p - d1;
        sm[aCUM + 2 * tid + 1] = p;
    }
    __syncthreads();

    // ---- phase 1: G = C @ B^T, decay mask -> W (1 row x 4 cols per thread) ----
    int s = tid >> 4;                // 0..63
    int ti = tid & 15;               // 0..15
    int sp0 = ti * 4;
    {
        float g[4] = {0.f, 0.f, 0.f, 0.f};
        for (int n = 0; n < 64; n += 2) {
            float2 cr = *(const float2*)&sm[aC + s * 66 + n];
            float4 b0 = *(const float4*)&sm[aBT + n * 68 + sp0];
            float4 b1 = *(const float4*)&sm[aBT + (n + 1) * 68 + sp0];
            g[0] += cr.x * b0.x + cr.y * b1.x;
            g[1] += cr.x * b0.y + cr.y * b1.y;
            g[2] += cr.x * b0.z + cr.y * b1.z;
            g[3] += cr.x * b0.w + cr.y * b1.w;
        }
        float cs = sm[aCUM + s];
        float4 w;
        float* wp = &w.x;
        #pragma unroll
        for (int j = 0; j < 4; j++) {
            int sp = sp0 + j;
            float v = 0.f;
            if (sp <= s)
                v = g[j] * __expf(a * (cs - sm[aCUM + sp])) * sm[aDT + sp];
            wp[j] = v;
        }
        *(float4*)&sm[aW + s * 68 + sp0] = w;
    }
    __syncthreads();

    // ---- phase 2: Y = W @ X + D*x (1 row x 4 cols), vectorized W+X reads ----
    {
        int p0 = ti * 4;
        float yv[4] = {0.f, 0.f, 0.f, 0.f};
        for (int sp = 0; sp < 64; sp += 4) {
            float4 w4 = *(const float4*)&sm[aW + s * 68 + sp];
            float4 x0 = *(const float4*)&sm[aX + (sp + 0) * 68 + p0];
            float4 x1 = *(const float4*)&sm[aX + (sp + 1) * 68 + p0];
            float4 x2 = *(const float4*)&sm[aX + (sp + 2) * 68 + p0];
            float4 x3 = *(const float4*)&sm[aX + (sp + 3) * 68 + p0];
            yv[0] += w4.x * x0.x; yv[1] += w4.x * x0.y; yv[2] += w4.x * x0.z; yv[3] += w4.x * x0.w;
            yv[0] += w4.y * x1.x; yv[1] += w4.y * x1.y; yv[2] += w4.y * x1.z; yv[3] += w4.y * x1.w;
            yv[0] += w4.z * x2.x; yv[1] += w4.z * x2.y; yv[2] += w4.z * x2.z; yv[3] += w4.z * x2.w;
            yv[0] += w4.w * x3.x; yv[1] += w4.w * x3.y; yv[2] += w4.w * x3.z; yv[3] += w4.w * x3.w;
        }
        float4 xq = *(const float4*)&sm[aX + s * 68 + p0];
        float4 o;
        o.x = yv[0] + dpar * xq.x;
        o.y = yv[1] + dpar * xq.y;
        o.z = yv[2] + dpar * xq.z;
        o.w = yv[3] + dpar * xq.w;
        int tok = dir ? (kL - 1 - s) : s;
        *(float4*)&y[(long)(b * kL + tok) * kDIN + h * kDH + p0] = o;
    }
}

// ---- gate + rmsnorm over DIN, both dirs ----
__global__ void k_gate_norm2(const float* __restrict__ zxbase,
                             const float* __restrict__ gn0, const float* __restrict__ gn1,
                             float* __restrict__ ybase) {
    int row = blockIdx.x;
    const float* gn = (row >= kTOK) ? gn1 : gn0;
    const float* zrow = zxbase + (long)row * kP;
    float* yrow = ybase + (long)row * kDIN;
    int t = threadIdx.x;
    float v0 = yrow[t] * siluf(zrow[t]);
    float v1 = yrow[t + 256] * siluf(zrow[t + 256]);
    float ss = block_reduce_sum_256(v0 * v0 + v1 * v1);
    float sc = rsqrtf(ss * (1.f / kDIN) + kEPS);
    yrow[t]       = v0 * sc * gn[t];
    yrow[t + 256] = v1 * sc * gn[t + 256];
}

// ---- fused mean-pool + classifier head; grid (kB, 5), 200 classes/block ----
__global__ void k_meanhead(const float* __restrict__ nx, const float* __restrict__ hw,
                           const float* __restrict__ hb, float* __restrict__ out) {
    int b = blockIdx.x;
    int c0 = blockIdx.y * 200;
    int t = threadIdx.x;
    __shared__ float pool[kD];
    float s = 0.f;
    #pragma unroll 8
    for (int l = 0; l < kL; l++) s += nx[(long)(b * kL + l) * kD + t];
    pool[t] = s * (1.f / kL);
    __syncthreads();
    for (int n = c0 + t; n < c0 + 200 && n < kCLS; n += 256) {
        float acc = hb[n];
        #pragma unroll 8
        for (int k = 0; k < kD; k++) acc += pool[k] * hw[(long)k * kCLS + n];
        out[(long)b * kCLS + n] = acc;
    }
}

// ---------------- launch ----------------
extern "C" void kernel_launch(void* const* d_in, const int* in_sizes, int n_in,
                              void* d_out, int out_size) {
    const float* x       = (const float*)d_in[0];
    const float* patch_w = (const float*)d_in[1];
    const float* patch_b = (const float*)d_in[2];
    const float* pos     = (const float*)d_in[3];
    const float* norms_w = (const float*)d_in[4];
    const float* final_w = (const float*)d_in[5];
    const float* head_w  = (const float*)d_in[6];
    const float* head_b  = (const float*)d_in[7];
    const float* Win[2]  = {(const float*)d_in[8],  (const float*)d_in[16]};
    const float* cw[2]   = {(const float*)d_in[9],  (const float*)d_in[17]};
    const float* cb[2]   = {(const float*)d_in[10], (const float*)d_in[18]};
    const float* dtb[2]  = {(const float*)d_in[11], (const float*)d_in[19]};
    const float* Alog[2] = {(const float*)d_in[12], (const float*)d_in[20]};
    const float* Dp[2]   = {(const float*)d_in[13], (const float*)d_in[21]};
    const float* gn[2]   = {(const float*)d_in[14], (const float*)d_in[22]};
    const float* Wout[2] = {(const float*)d_in[15], (const float*)d_in[23]};
    float* out = (float*)d_out;

    float *p_t, *p_nx, *p_zx, *p_y, *p_o;
    cudaGetSymbolAddress((void**)&p_t, g_t);
    cudaGetSymbolAddress((void**)&p_nx, g_nx);
    cudaGetSymbolAddress((void**)&p_zx, g_zx);
    cudaGetSymbolAddress((void**)&p_y, g_y);
    cudaGetSymbolAddress((void**)&p_o, g_o);

    const int smem64  = (2 * 64 * kAStride + 2 * kBStage) * 4;
    cudaFuncSetAttribute(k_gemm_tc<64>,  cudaFuncAttributeMaxDynamicSharedMemorySize, smem64);
    cudaFuncSetAttribute(k_attn, cudaFuncAttributeMaxDynamicSharedMemorySize, kAttnSmemBytes);

    // stem: fused patchify + GEMM + bias + pos
    {
        dim3 g(kD / 64, kTOK / 64);
        k_gemm_patch<<<g, 256>>>(x, patch_w, patch_b, pos, p_t);
    }

    for (int i = 0; i < 2; i++) {
        if (i == 0)
            k_resnorm<<<kTOK, 256>>>(p_t, p_o, p_o, norms_w, p_nx, 0);
        else
            k_resnorm<<<kTOK, 256>>>(p_t, p_o, p_o + kTOK * kD, norms_w + kD, p_nx, 1);
        {
            dim3 g((kP + 63) / 64, kTOK / 64, 2);
            k_gemm_tc<64><<<g, 256, smem64>>>(p_nx, Win[0] + i * kD * kP, Win[1] + i * kD * kP,
                                              p_zx, kTOK, kP, kD, 0, (long)kTOK * kP);
        }
        {
            dim3 g(kB, kH, 2);
            k_attn<<<g, 1024, kAttnSmemBytes>>>(p_zx,
                                    cw[0] + i * kCDIM * 4, cw[1] + i * kCDIM * 4,
                                    cb[0] + i * kCDIM, cb[1] + i * kCDIM,
                                    dtb[0] + i * kH, dtb[1] + i * kH,
                                    Alog[0] + i * kH, Alog[1] + i * kH,
                                    Dp[0] + i * kH, Dp[1] + i * kH, p_y);
        }
        k_gate_norm2<<<2 * kTOK, 256>>>(p_zx, gn[0] + i * kDIN, gn[1] + i * kDIN, p_y);
        {
            dim3 g(kD / 64, kTOK / 64, 2);
            k_gemm_tc<64><<<g, 256, smem64>>>(p_y, Wout[0] + i * kDIN * kD, Wout[1] + i * kDIN * kD,
                                              p_o, kTOK, kD, kDIN, (long)kTOK * kDIN, (long)kTOK * kD);
        }
    }

    // final residual + norm, then fused mean+head
    k_resnorm<<<kTOK, 256>>>(p_t, p_o, p_o + kTOK * kD, final_w, p_nx, 1);
    k_meanhead<<<dim3(kB, 5), 256>>>(p_nx, head_w, head_b, out);
}

// round 10
// speedup vs baseline: 1.0860x; 1.0860x over previous
#include <cuda_runtime.h>
#include <math.h>

// ---------------- problem constants ----------------
constexpr int kB    = 16;
constexpr int kL    = 64;
constexpr int kD    = 256;
constexpr int kDIN  = 512;
constexpr int kH    = 8;
constexpr int kDH   = 64;
constexpr int kN    = 64;
constexpr int kCDIM = 640;
constexpr int kP    = 1160;
constexpr int kPF   = 768;
constexpr int kCLS  = 1000;
constexpr float kEPS = 1e-6f;
constexpr int kTOK  = kB * kL;  // 1024

// GEMM smem geometry (floats)
constexpr int kAStride = 36;
constexpr int kBStride = 72;
constexpr int kBStage  = 32 * kBStride;      // 2304

// attn kernel smem layout (floats) — all strides float4-friendly
constexpr int aW   = 0;          // 64*68 (raw staging, then W)
constexpr int aX   = 4352;       // 64*68
constexpr int aBT  = 8704;       // 64*68  (B transposed: [n][s'])
constexpr int aC   = 13056;      // 64*66
constexpr int aDT  = 17280;      // 64
constexpr int aCUM = 17344;      // 64
constexpr int kAttnSmemBytes = 17408 * 4;    // 69632

// ---------------- scratch ----------------
__device__ float g_t[kTOK*kD];
__device__ float g_nx[kTOK*kD];
__device__ float g_zx[2][kTOK*kP];
__device__ float g_y[2][kTOK*kDIN];
__device__ float g_o[2][kTOK*kD];

// ---------------- helpers ----------------
__device__ __forceinline__ int snake_src(int l) {
    int r = l >> 3, c = l & 7;
    return r * 8 + ((r & 1) ? (7 - c) : c);
}

__device__ __forceinline__ float block_reduce_sum_256(float v) {
    __shared__ float sh[8];
    __shared__ float tot;
    int lane = threadIdx.x & 31, w = threadIdx.x >> 5;
    #pragma unroll
    for (int o = 16; o > 0; o >>= 1) v += __shfl_xor_sync(0xffffffffu, v, o);
    if (lane == 0) sh[w] = v;
    __syncthreads();
    if (w == 0) {
        float x = (lane < 8) ? sh[lane] : 0.f;
        #pragma unroll
        for (int o = 4; o > 0; o >>= 1) x += __shfl_xor_sync(0xffffffffu, x, o);
        if (lane == 0) tot = x;
    }
    __syncthreads();
    return tot;
}

__device__ __forceinline__ float siluf(float x) {
    return x / (1.f + expf(-x));
}

__device__ __forceinline__ unsigned f2tf32(float f) {
    unsigned r;
    asm("cvt.rna.tf32.f32 %0, %1;" : "=r"(r) : "f"(f));
    return r;
}

__device__ __forceinline__ void cpa16(float* dst, const float* src) {
    unsigned d = (unsigned)__cvta_generic_to_shared(dst);
    asm volatile("cp.async.cg.shared.global [%0], [%1], 16;" :: "r"(d), "l"(src));
}

// ---------------- kernels ----------------

// ---- patch GEMM: 64x64 tiles (fused patchify + transpose-B + bias + pos) ----
__global__ void __launch_bounds__(256) k_gemm_patch(
        const float* __restrict__ x, const float* __restrict__ Bw,
        const float* __restrict__ pb, const float* __restrict__ pos,
        float* __restrict__ C) {
    __shared__ unsigned As[16][72];
    __shared__ unsigned Bs[16][72];
    int tid = threadIdx.x;
    int lane = tid & 31, warp = tid >> 5;
    int lg = lane >> 2, lt = lane & 3;
    int wm = (warp >> 2) * 32;
    int wn = (warp & 3) * 16;
    int m0 = blockIdx.y * 64, n0 = blockIdx.x * 64;

    float c[2][2][4];
    #pragma unroll
    for (int a = 0; a < 2; a++)
        #pragma unroll
        for (int b = 0; b < 2; b++)
            #pragma unroll
            for (int d = 0; d < 4; d++) c[a][b][d] = 0.f;

    int am = tid >> 2;
    int ak = (tid & 3) * 4;
    int bk = tid >> 4;
    int bn = (tid & 15) * 4;

    int m = m0 + am;
    int bimg = m >> 6, l = m & 63;
    int src = snake_src(l);
    int gr = src >> 3, gc = src & 7;

    for (int k0 = 0; k0 < kPF; k0 += 16) {
        {
            int f = k0 + ak;
            int ch = f >> 8, rem = f & 255;
            int pr = rem >> 4, pc = rem & 15;
            const float* ap = x + ((long)(bimg * 3 + ch) * 128 + gr * 16 + pr) * 128
                                + gc * 16 + pc;
            float4 v = *(const float4*)(ap);
            As[ak + 0][am] = f2tf32(v.x);
            As[ak + 1][am] = f2tf32(v.y);
            As[ak + 2][am] = f2tf32(v.z);
            As[ak + 3][am] = f2tf32(v.w);
        }
        {
            #pragma unroll
            for (int j = 0; j < 4; j++)
                Bs[bk][bn + j] = f2tf32(Bw[(long)(n0 + bn + j) * kPF + k0 + bk]);
        }
        __syncthreads();
        #pragma unroll
        for (int k8 = 0; k8 < 16; k8 += 8) {
            unsigned afr[2][4], bfr[2][2];
            #pragma unroll
            for (int mt = 0; mt < 2; mt++) {
                int mb = wm + mt * 16;
                afr[mt][0] = As[k8 + lt][mb + lg];
                afr[mt][1] = As[k8 + lt][mb + 8 + lg];
                afr[mt][2] = As[k8 + lt + 4][mb + lg];
                afr[mt][3] = As[k8 + lt + 4][mb + 8 + lg];
            }
            #pragma unroll
            for (int nt = 0; nt < 2; nt++) {
                bfr[nt][0] = Bs[k8 + lt][wn + nt * 8 + lg];
                bfr[nt][1] = Bs[k8 + lt + 4][wn + nt * 8 + lg];
            }
            #pragma unroll
            for (int mt = 0; mt < 2; mt++)
                #pragma unroll
                for (int nt = 0; nt < 2; nt++)
                    asm volatile(
                        "mma.sync.aligned.m16n8k8.row.col.f32.tf32.tf32.f32 "
                        "{%0,%1,%2,%3}, {%4,%5,%6,%7}, {%8,%9}, {%0,%1,%2,%3};"
                        : "+f"(c[mt][nt][0]), "+f"(c[mt][nt][1]),
                          "+f"(c[mt][nt][2]), "+f"(c[mt][nt][3])
                        : "r"(afr[mt][0]), "r"(afr[mt][1]),
                          "r"(afr[mt][2]), "r"(afr[mt][3]),
                          "r"(bfr[nt][0]), "r"(bfr[nt][1]));
        }
        __syncthreads();
    }

    #pragma unroll
    for (int mt = 0; mt < 2; mt++) {
        int r0 = m0 + wm + mt * 16 + lg;
        int l0 = r0 & 63, l8 = (r0 + 8) & 63;
        int s0 = snake_src(l0) * kD, s8 = snake_src(l8) * kD;
        #pragma unroll
        for (int nt = 0; nt < 2; nt++) {
            int gn = n0 + wn + nt * 8 + 2 * lt;
            C[(long)r0 * kD + gn]           = c[mt][nt][0] + pb[gn] + pos[s0 + gn];
            C[(long)r0 * kD + gn + 1]       = c[mt][nt][1] + pb[gn + 1] + pos[s0 + gn + 1];
            C[(long)(r0 + 8) * kD + gn]     = c[mt][nt][2] + pb[gn] + pos[s8 + gn];
            C[(long)(r0 + 8) * kD + gn + 1] = c[mt][nt][3] + pb[gn + 1] + pos[s8 + gn + 1];
        }
    }
}

// ---- TF32 GEMM, cp.async double-buffered, K-step 32, templated M-tile ----
template<int MT>
__global__ void __launch_bounds__(256) k_gemm_tc(
        const float* __restrict__ Abase,
        const float* __restrict__ B0, const float* __restrict__ B1,
        float* __restrict__ Cbase,
        int M, int N, int K, long sA, long sC) {
    extern __shared__ float smem[];
    constexpr int NTF = (MT == 128) ? 4 : 2;
    constexpr int ASTAGE = MT * kAStride;
    constexpr int BBASE = 2 * ASTAGE;
    int z = blockIdx.z;
    const float* A = Abase + (long)z * sA;
    const float* B = z ? B1 : B0;
    float* C = Cbase + (long)z * sC;
    int tid = threadIdx.x;
    int lane = tid & 31, warp = tid >> 5;
    int lg = lane >> 2, lt = lane & 3;
    int wm = (MT == 128) ? (warp >> 1) * 32 : (warp >> 2) * 32;
    int wn = (MT == 128) ? (warp & 1) * 32 : (warp & 3) * 16;
    int m0 = blockIdx.y * MT, n0 = blockIdx.x * 64;

    float c[2][NTF][4];
    #pragma unroll
    for (int a = 0; a < 2; a++)
        #pragma unroll
        for (int b = 0; b < NTF; b++)
            #pragma unroll
            for (int d = 0; d < 4; d++) c[a][b][d] = 0.f;

    int am = (MT == 128) ? (tid >> 1) : (tid >> 2);
    int ak = (MT == 128) ? (tid & 1) * 16 : (tid & 3) * 8;
    int bk = tid >> 3, bn = (tid & 7) * 8;

    if (n0 + 64 > N) {
        for (int i = tid; i < 2 * kBStage; i += 256) smem[BBASE + i] = 0.f;
        __syncthreads();
    }

    int nIters = K >> 5;

    {
        const float* ap = A + (long)(m0 + am) * K + ak;
        float* ad = &smem[am * kAStride + ak];
        cpa16(ad, ap); cpa16(ad + 4, ap + 4);
        if (MT == 128) { cpa16(ad + 8, ap + 8); cpa16(ad + 12, ap + 12); }
        const float* bp = B + (long)bk * N + n0 + bn;
        float* bd = &smem[BBASE + bk * kBStride + bn];
        if (n0 + bn < N) cpa16(bd, bp);
        if (n0 + bn + 4 < N) cpa16(bd + 4, bp + 4);
        asm volatile("cp.async.commit_group;");
    }

    for (int it = 0; it < nIters; it++) {
        if (it + 1 < nIters) {
            int k0 = (it + 1) << 5;
            int st = (it + 1) & 1;
            const float* ap = A + (long)(m0 + am) * K + k0 + ak;
            float* ad = &smem[st * ASTAGE + am * kAStride + ak];
            cpa16(ad, ap); cpa16(ad + 4, ap + 4);
            if (MT == 128) { cpa16(ad + 8, ap + 8); cpa16(ad + 12, ap + 12); }
            const float* bp = B + (long)(k0 + bk) * N + n0 + bn;
            float* bd = &smem[BBASE + st * kBStage + bk * kBStride + bn];
            if (n0 + bn < N) cpa16(bd, bp);
            if (n0 + bn + 4 < N) cpa16(bd + 4, bp + 4);
            asm volatile("cp.async.commit_group;");
            asm volatile("cp.async.wait_group 1;");
        } else {
            asm volatile("cp.async.wait_group 0;");
        }
        __syncthreads();

        const float* Ab = &smem[(it & 1) * ASTAGE];
        const float* Bb = &smem[BBASE + (it & 1) * kBStage];
        #pragma unroll
        for (int k8 = 0; k8 < 32; k8 += 8) {
            unsigned afr[2][4], bfr[NTF][2];
            #pragma unroll
            for (int mt = 0; mt < 2; mt++) {
                int mb = wm + mt * 16;
                afr[mt][0] = f2tf32(Ab[(mb + lg) * kAStride + k8 + lt]);
                afr[mt][1] = f2tf32(Ab[(mb + 8 + lg) * kAStride + k8 + lt]);
                afr[mt][2] = f2tf32(Ab[(mb + lg) * kAStride + k8 + lt + 4]);
                afr[mt][3] = f2tf32(Ab[(mb + 8 + lg) * kAStride + k8 + lt + 4]);
            }
            #pragma unroll
            for (int nt = 0; nt < NTF; nt++) {
                bfr[nt][0] = f2tf32(Bb[(k8 + lt) * kBStride + wn + nt * 8 + lg]);
                bfr[nt][1] = f2tf32(Bb[(k8 + lt + 4) * kBStride + wn + nt * 8 + lg]);
            }
            #pragma unroll
            for (int mt = 0; mt < 2; mt++)
                #pragma unroll
                for (int nt = 0; nt < NTF; nt++)
                    asm volatile(
                        "mma.sync.aligned.m16n8k8.row.col.f32.tf32.tf32.f32 "
                        "{%0,%1,%2,%3}, {%4,%5,%6,%7}, {%8,%9}, {%0,%1,%2,%3};"
                        : "+f"(c[mt][nt][0]), "+f"(c[mt][nt][1]),
                          "+f"(c[mt][nt][2]), "+f"(c[mt][nt][3])
                        : "r"(afr[mt][0]), "r"(afr[mt][1]),
                          "r"(afr[mt][2]), "r"(afr[mt][3]),
                          "r"(bfr[nt][0]), "r"(bfr[nt][1]));
        }
        __syncthreads();
    }

    #pragma unroll
    for (int mt = 0; mt < 2; mt++) {
        int r0 = m0 + wm + mt * 16 + lg;
        #pragma unroll
        for (int nt = 0; nt < NTF; nt++) {
            int gn = n0 + wn + nt * 8 + 2 * lt;
            if (gn < N) {
                C[(long)r0 * N + gn] = c[mt][nt][0];
                C[(long)(r0 + 8) * N + gn] = c[mt][nt][2];
                if (gn + 1 < N) {
                    C[(long)r0 * N + gn + 1] = c[mt][nt][1];
                    C[(long)(r0 + 8) * N + gn + 1] = c[mt][nt][3];
                }
            }
        }
    }
}

// ---- fused residual + rmsnorm ----
__global__ void k_resnorm(float* __restrict__ t, const float* __restrict__ o0,
                          const float* __restrict__ o1, const float* __restrict__ w,
                          float* __restrict__ nx, int addRes) {
    int row = blockIdx.x;
    int d = threadIdx.x;
    long i = (long)row * kD + d;
    float v = t[i];
    if (addRes) {
        v += 0.5f * (o0[i] + o1[i]);
        t[i] = v;
    }
    float ss = block_reduce_sum_256(v * v);
    nx[i] = v * rsqrtf(ss * (1.f / kD) + kEPS) * w[d];
}

// ---- chunked dual-form "scan": conv + dt + decay-masked attention ----
// grid (kB, kH, 2), 512 threads; 2x4 tiles + fully vectorized shared traffic.
__global__ void __launch_bounds__(512) k_attn(
        const float* __restrict__ zxbase,
        const float* __restrict__ cw0, const float* __restrict__ cw1,
        const float* __restrict__ cb0, const float* __restrict__ cb1,
        const float* __restrict__ dtb0, const float* __restrict__ dtb1,
        const float* __restrict__ Alog0, const float* __restrict__ Alog1,
        const float* __restrict__ Dp0, const float* __restrict__ Dp1,
        float* __restrict__ ybase) {
    extern __shared__ float sm[];
    int b = blockIdx.x, h = blockIdx.y, dir = blockIdx.z;
    const float* zx = zxbase + (long)dir * kTOK * kP;
    float* y        = ybase  + (long)dir * kTOK * kDIN;
    const float* cw  = dir ? cw1 : cw0;
    const float* cb  = dir ? cb1 : cb0;
    float a = -expf((dir ? Alog1 : Alog0)[h]);
    float dpar = (dir ? Dp1 : Dp0)[h];
    float dtbv = (dir ? dtb1 : dtb0)[h];
    int tid = threadIdx.x;
    int nthr = blockDim.x;   // 512

    // ---- phase 0: conv + silu into sX [s][p], sBT [n][s'], sC [s][n] ----
    #pragma unroll
    for (int seg = 0; seg < 3; seg++) {
        int off = (seg == 0) ? h * kDH : (seg == 1) ? kDIN : kDIN + kN;
        // stage raw via float4 (1024 quads over 512 threads)
        for (int idx = tid; idx < 1024; idx += nthr) {
            int s = idx >> 4, q = (idx & 15) * 4;
            int tok = dir ? (kL - 1 - s) : s;
            float4 v = *(const float4*)&zx[(long)(b * kL + tok) * kP + kDIN + off + q];
            *(float4*)&sm[aW + s * 68 + q] = v;
        }
        __syncthreads();
        if (seg == 1) {
            for (int idx = tid; idx < 4096; idx += nthr) {
                int s = idx & 63, cc = idx >> 6;
                float acc = cb[off + cc];
                #pragma unroll
                for (int k = 0; k < 4; k++) {
                    int sp = s - 3 + k;
                    if (sp >= 0) acc += cw[(off + cc) * 4 + k] * sm[aW + sp * 68 + cc];
                }
                sm[aBT + cc * 68 + s] = siluf(acc);
            }
        } else {
            int dst = (seg == 0) ? aX : aC;
            int stride = (seg == 0) ? 68 : 66;
            for (int idx = tid; idx < 4096; idx += nthr) {
                int s = idx >> 6, cc = idx & 63;
                float acc = cb[off + cc];
                #pragma unroll
                for (int k = 0; k < 4; k++) {
                    int sp = s - 3 + k;
                    if (sp >= 0) acc += cw[(off + cc) * 4 + k] * sm[aW + sp * 68 + cc];
                }
                sm[dst + s * stride + cc] = siluf(acc);
            }
        }
        __syncthreads();
    }

    // dt (softplus) + inclusive cumsum
    if (tid < 64) {
        int s = tid;
        int tok = dir ? (kL - 1 - s) : s;
        float v = zx[(long)(b * kL + tok) * kP + 2 * kDIN + 2 * kN + h] + dtbv;
        sm[aDT + s] = (v > 20.f) ? v : log1pf(expf(v));
    }
    __syncthreads();
    if (tid < 32) {
        float d0 = sm[aDT + 2 * tid], d1 = sm[aDT + 2 * tid + 1];
        float p = d0 + d1;
        #pragma unroll
        for (int o = 1; o < 32; o <<= 1) {
            float t = __shfl_up_sync(0xffffffffu, p, o);
            if (tid >= o) p += t;
        }
        sm[aCUM + 2 * tid] = p - d1;
        sm[aCUM + 2 * tid + 1] = p;
    }
    __syncthreads();

    // ---- phase 1: G = C @ B^T, decay mask -> W (2 rows x 4 cols/thread) ----
    int rg = tid >> 4;               // 0..31
    int ti = tid & 15;               // 0..15
    int s0 = rg * 2, sp0 = ti * 4;
    {
        float g[2][4];
        #pragma unroll
        for (int r = 0; r < 2; r++)
            #pragma unroll
            for (int j = 0; j < 4; j++) g[r][j] = 0.f;
        for (int n = 0; n < 64; n += 2) {
            float2 cr[2];
            #pragma unroll
            for (int r = 0; r < 2; r++)
                cr[r] = *(const float2*)&sm[aC + (s0 + r) * 66 + n];
            float4 b0 = *(const float4*)&sm[aBT + n * 68 + sp0];
            float4 b1 = *(const float4*)&sm[aBT + (n + 1) * 68 + sp0];
            #pragma unroll
            for (int r = 0; r < 2; r++) {
                g[r][0] += cr[r].x * b0.x + cr[r].y * b1.x;
                g[r][1] += cr[r].x * b0.y + cr[r].y * b1.y;
                g[r][2] += cr[r].x * b0.z + cr[r].y * b1.z;
                g[r][3] += cr[r].x * b0.w + cr[r].y * b1.w;
            }
        }
        #pragma unroll
        for (int r = 0; r < 2; r++) {
            int s = s0 + r;
            float cs = sm[aCUM + s];
            float4 w;
            float* wp = &w.x;
            #pragma unroll
            for (int j = 0; j < 4; j++) {
                int sp = sp0 + j;
                float v = 0.f;
                if (sp <= s)
                    v = g[r][j] * __expf(a * (cs - sm[aCUM + sp])) * sm[aDT + sp];
                wp[j] = v;
            }
            *(float4*)&sm[aW + s * 68 + sp0] = w;
        }
    }
    __syncthreads();

    // ---- phase 2: Y = W @ X + D*x (2 rows x 4 cols), float4 W + X reads ----
    {
        int p0 = ti * 4;
        float yv[2][4];
        #pragma unroll
        for (int r = 0; r < 2; r++)
            #pragma unroll
            for (int j = 0; j < 4; j++) yv[r][j] = 0.f;
        for (int sp = 0; sp < 64; sp += 4) {
            float4 w0 = *(const float4*)&sm[aW + (s0 + 0) * 68 + sp];
            float4 w1 = *(const float4*)&sm[aW + (s0 + 1) * 68 + sp];
            float4 x0 = *(const float4*)&sm[aX + (sp + 0) * 68 + p0];
            float4 x1 = *(const float4*)&sm[aX + (sp + 1) * 68 + p0];
            float4 x2 = *(const float4*)&sm[aX + (sp + 2) * 68 + p0];
            float4 x3 = *(const float4*)&sm[aX + (sp + 3) * 68 + p0];
            yv[0][0] += w0.x * x0.x; yv[0][1] += w0.x * x0.y; yv[0][2] += w0.x * x0.z; yv[0][3] += w0.x * x0.w;
            yv[0][0] += w0.y * x1.x; yv[0][1] += w0.y * x1.y; yv[0][2] += w0.y * x1.z; yv[0][3] += w0.y * x1.w;
            yv[0][0] += w0.z * x2.x; yv[0][1] += w0.z * x2.y; yv[0][2] += w0.z * x2.z; yv[0][3] += w0.z * x2.w;
            yv[0][0] += w0.w * x3.x; yv[0][1] += w0.w * x3.y; yv[0][2] += w0.w * x3.z; yv[0][3] += w0.w * x3.w;
            yv[1][0] += w1.x * x0.x; yv[1][1] += w1.x * x0.y; yv[1][2] += w1.x * x0.z; yv[1][3] += w1.x * x0.w;
            yv[1][0] += w1.y * x1.x; yv[1][1] += w1.y * x1.y; yv[1][2] += w1.y * x1.z; yv[1][3] += w1.y * x1.w;
            yv[1][0] += w1.z * x2.x; yv[1][1] += w1.z * x2.y; yv[1][2] += w1.z * x2.z; yv[1][3] += w1.z * x2.w;
            yv[1][0] += w1.w * x3.x; yv[1][1] += w1.w * x3.y; yv[1][2] += w1.w * x3.z; yv[1][3] += w1.w * x3.w;
        }
        #pragma unroll
        for (int r = 0; r < 2; r++) {
            int s = s0 + r;
            float4 xq = *(const float4*)&sm[aX + s * 68 + p0];
            float4 o;
            o.x = yv[r][0] + dpar * xq.x;
            o.y = yv[r][1] + dpar * xq.y;
            o.z = yv[r][2] + dpar * xq.z;
            o.w = yv[r][3] + dpar * xq.w;
            int tok = dir ? (kL - 1 - s) : s;
            *(float4*)&y[(long)(b * kL + tok) * kDIN + h * kDH + p0] = o;
        }
    }
}

// ---- gate + rmsnorm over DIN, both dirs ----
__global__ void k_gate_norm2(const float* __restrict__ zxbase,
                             const float* __restrict__ gn0, const float* __restrict__ gn1,
                             float* __restrict__ ybase) {
    int row = blockIdx.x;
    const float* gn = (row >= kTOK) ? gn1 : gn0;
    const float* zrow = zxbase + (long)row * kP;
    float* yrow = ybase + (long)row * kDIN;
    int t = threadIdx.x;
    float v0 = yrow[t] * siluf(zrow[t]);
    float v1 = yrow[t + 256] * siluf(zrow[t + 256]);
    float ss = block_reduce_sum_256(v0 * v0 + v1 * v1);
    float sc = rsqrtf(ss * (1.f / kDIN) + kEPS);
    yrow[t]       = v0 * sc * gn[t];
    yrow[t + 256] = v1 * sc * gn[t + 256];
}

// ---- fused mean-pool + classifier head; grid (kB, 5), 200 classes/block ----
__global__ void k_meanhead(const float* __restrict__ nx, const float* __restrict__ hw,
                           const float* __restrict__ hb, float* __restrict__ out) {
    int b = blockIdx.x;
    int c0 = blockIdx.y * 200;
    int t = threadIdx.x;
    __shared__ float pool[kD];
    float s = 0.f;
    #pragma unroll 8
    for (int l = 0; l < kL; l++) s += nx[(long)(b * kL + l) * kD + t];
    pool[t] = s * (1.f / kL);
    __syncthreads();
    for (int n = c0 + t; n < c0 + 200 && n < kCLS; n += 256) {
        float acc = hb[n];
        #pragma unroll 8
        for (int k = 0; k < kD; k++) acc += pool[k] * hw[(long)k * kCLS + n];
        out[(long)b * kCLS + n] = acc;
    }
}

// ---------------- launch ----------------
extern "C" void kernel_launch(void* const* d_in, const int* in_sizes, int n_in,
                              void* d_out, int out_size) {
    const float* x       = (const float*)d_in[0];
    const float* patch_w = (const float*)d_in[1];
    const float* patch_b = (const float*)d_in[2];
    const float* pos     = (const float*)d_in[3];
    const float* norms_w = (const float*)d_in[4];
    const float* final_w = (const float*)d_in[5];
    const float* head_w  = (const float*)d_in[6];
    const float* head_b  = (const float*)d_in[7];
    const float* Win[2]  = {(const float*)d_in[8],  (const float*)d_in[16]};
    const float* cw[2]   = {(const float*)d_in[9],  (const float*)d_in[17]};
    const float* cb[2]   = {(const float*)d_in[10], (const float*)d_in[18]};
    const float* dtb[2]  = {(const float*)d_in[11], (const float*)d_in[19]};
    const float* Alog[2] = {(const float*)d_in[12], (const float*)d_in[20]};
    const float* Dp[2]   = {(const float*)d_in[13], (const float*)d_in[21]};
    const float* gn[2]   = {(const float*)d_in[14], (const float*)d_in[22]};
    const float* Wout[2] = {(const float*)d_in[15], (const float*)d_in[23]};
    float* out = (float*)d_out;

    float *p_t, *p_nx, *p_zx, *p_y, *p_o;
    cudaGetSymbolAddress((void**)&p_t, g_t);
    cudaGetSymbolAddress((void**)&p_nx, g_nx);
    cudaGetSymbolAddress((void**)&p_zx, g_zx);
    cudaGetSymbolAddress((void**)&p_y, g_y);
    cudaGetSymbolAddress((void**)&p_o, g_o);

    const int smem64  = (2 * 64 * kAStride + 2 * kBStage) * 4;
    cudaFuncSetAttribute(k_gemm_tc<64>,  cudaFuncAttributeMaxDynamicSharedMemorySize, smem64);
    cudaFuncSetAttribute(k_attn, cudaFuncAttributeMaxDynamicSharedMemorySize, kAttnSmemBytes);

    // stem: fused patchify + GEMM + bias + pos
    {
        dim3 g(kD / 64, kTOK / 64);
        k_gemm_patch<<<g, 256>>>(x, patch_w, patch_b, pos, p_t);
    }

    for (int i = 0; i < 2; i++) {
        if (i == 0)
            k_resnorm<<<kTOK, 256>>>(p_t, p_o, p_o, norms_w, p_nx, 0);
        else
            k_resnorm<<<kTOK, 256>>>(p_t, p_o, p_o + kTOK * kD, norms_w + kD, p_nx, 1);
        {
            dim3 g((kP + 63) / 64, kTOK / 64, 2);
            k_gemm_tc<64><<<g, 256, smem64>>>(p_nx, Win[0] + i * kD * kP, Win[1] + i * kD * kP,
                                              p_zx, kTOK, kP, kD, 0, (long)kTOK * kP);
        }
        {
            dim3 g(kB, kH, 2);
            k_attn<<<g, 512, kAttnSmemBytes>>>(p_zx,
                                    cw[0] + i * kCDIM * 4, cw[1] + i * kCDIM * 4,
                                    cb[0] + i * kCDIM, cb[1] + i * kCDIM,
                                    dtb[0] + i * kH, dtb[1] + i * kH,
                                    Alog[0] + i * kH, Alog[1] + i * kH,
                                    Dp[0] + i * kH, Dp[1] + i * kH, p_y);
        }
        k_gate_norm2<<<2 * kTOK, 256>>>(p_zx, gn[0] + i * kDIN, gn[1] + i * kDIN, p_y);
        {
            dim3 g(kD / 64, kTOK / 64, 2);
            k_gemm_tc<64><<<g, 256, smem64>>>(p_y, Wout[0] + i * kDIN * kD, Wout[1] + i * kDIN * kD,
                                              p_o, kTOK, kD, kDIN, (long)kTOK * kDIN, (long)kTOK * kD);
        }
    }

    // final residual + norm, then fused mean+head
    k_resnorm<<<kTOK, 256>>>(p_t, p_o, p_o + kTOK * kD, final_w, p_nx, 1);
    k_meanhead<<<dim3(kB, 5), 256>>>(p_nx, head_w, head_b, out);
}

// round 11
// speedup vs baseline: 1.1856x; 1.0917x over previous
#include <cuda_runtime.h>
#include <math.h>

// ---------------- problem constants ----------------
constexpr int kB    = 16;
constexpr int kL    = 64;
constexpr int kD    = 256;
constexpr int kDIN  = 512;
constexpr int kH    = 8;
constexpr int kDH   = 64;
constexpr int kN    = 64;
constexpr int kCDIM = 640;
constexpr int kP    = 1160;
constexpr int kPF   = 768;
constexpr int kCLS  = 1000;
constexpr float kEPS = 1e-6f;
constexpr int kTOK  = kB * kL;  // 1024

// GEMM smem geometry (floats)
constexpr int kAStride = 36;
constexpr int kBStride = 72;
constexpr int kBStage  = 32 * kBStride;      // 2304

// attn kernel smem layout (floats), stride 68 everywhere
constexpr int aST  = 0;          // raw staging 64*68
constexpr int aXT  = 4352;       // X transposed [p][s'] 64*68 (GEMM2 B-operand)
constexpr int aBm  = 8704;       // B [s'][n] 64*68 (GEMM1 B-operand)
constexpr int aCm  = 13056;      // C [s][n] 64*68 (GEMM1 A); reused as W [s][s'] (GEMM2 A)
constexpr int aDT  = 17408;      // 64
constexpr int aCUM = 17472;      // 64
constexpr int kAttnSmemBytes = 17536 * 4;    // 70144

// ---------------- scratch ----------------
__device__ float g_t[kTOK*kD];
__device__ float g_nx[kTOK*kD];
__device__ float g_zx[2][kTOK*kP];
__device__ float g_y[2][kTOK*kDIN];
__device__ float g_o[2][kTOK*kD];

// ---------------- helpers ----------------
__device__ __forceinline__ int snake_src(int l) {
    int r = l >> 3, c = l & 7;
    return r * 8 + ((r & 1) ? (7 - c) : c);
}

__device__ __forceinline__ float block_reduce_sum_256(float v) {
    __shared__ float sh[8];
    __shared__ float tot;
    int lane = threadIdx.x & 31, w = threadIdx.x >> 5;
    #pragma unroll
    for (int o = 16; o > 0; o >>= 1) v += __shfl_xor_sync(0xffffffffu, v, o);
    if (lane == 0) sh[w] = v;
    __syncthreads();
    if (w == 0) {
        float x = (lane < 8) ? sh[lane] : 0.f;
        #pragma unroll
        for (int o = 4; o > 0; o >>= 1) x += __shfl_xor_sync(0xffffffffu, x, o);
        if (lane == 0) tot = x;
    }
    __syncthreads();
    return tot;
}

__device__ __forceinline__ float siluf(float x) {
    return x / (1.f + expf(-x));
}

__device__ __forceinline__ unsigned f2tf32(float f) {
    unsigned r;
    asm("cvt.rna.tf32.f32 %0, %1;" : "=r"(r) : "f"(f));
    return r;
}

__device__ __forceinline__ void cpa16(float* dst, const float* src) {
    unsigned d = (unsigned)__cvta_generic_to_shared(dst);
    asm volatile("cp.async.cg.shared.global [%0], [%1], 16;" :: "r"(d), "l"(src));
}

__device__ __forceinline__ void mma_tf32(float c[4], const unsigned a[4],
                                         unsigned b0, unsigned b1) {
    asm volatile(
        "mma.sync.aligned.m16n8k8.row.col.f32.tf32.tf32.f32 "
        "{%0,%1,%2,%3}, {%4,%5,%6,%7}, {%8,%9}, {%0,%1,%2,%3};"
        : "+f"(c[0]), "+f"(c[1]), "+f"(c[2]), "+f"(c[3])
        : "r"(a[0]), "r"(a[1]), "r"(a[2]), "r"(a[3]), "r"(b0), "r"(b1));
}

// ---------------- kernels ----------------

// ---- patch GEMM: 64x64 tiles (fused patchify + transpose-B + bias + pos) ----
__global__ void __launch_bounds__(256) k_gemm_patch(
        const float* __restrict__ x, const float* __restrict__ Bw,
        const float* __restrict__ pb, const float* __restrict__ pos,
        float* __restrict__ C) {
    __shared__ unsigned As[16][72];
    __shared__ unsigned Bs[16][72];
    int tid = threadIdx.x;
    int lane = tid & 31, warp = tid >> 5;
    int lg = lane >> 2, lt = lane & 3;
    int wm = (warp >> 2) * 32;
    int wn = (warp & 3) * 16;
    int m0 = blockIdx.y * 64, n0 = blockIdx.x * 64;

    float c[2][2][4];
    #pragma unroll
    for (int a = 0; a < 2; a++)
        #pragma unroll
        for (int b = 0; b < 2; b++)
            #pragma unroll
            for (int d = 0; d < 4; d++) c[a][b][d] = 0.f;

    int am = tid >> 2;
    int ak = (tid & 3) * 4;
    int bk = tid >> 4;
    int bn = (tid & 15) * 4;

    int m = m0 + am;
    int bimg = m >> 6, l = m & 63;
    int src = snake_src(l);
    int gr = src >> 3, gc = src & 7;

    for (int k0 = 0; k0 < kPF; k0 += 16) {
        {
            int f = k0 + ak;
            int ch = f >> 8, rem = f & 255;
            int pr = rem >> 4, pc = rem & 15;
            const float* ap = x + ((long)(bimg * 3 + ch) * 128 + gr * 16 + pr) * 128
                                + gc * 16 + pc;
            float4 v = *(const float4*)(ap);
            As[ak + 0][am] = f2tf32(v.x);
            As[ak + 1][am] = f2tf32(v.y);
            As[ak + 2][am] = f2tf32(v.z);
            As[ak + 3][am] = f2tf32(v.w);
        }
        {
            #pragma unroll
            for (int j = 0; j < 4; j++)
                Bs[bk][bn + j] = f2tf32(Bw[(long)(n0 + bn + j) * kPF + k0 + bk]);
        }
        __syncthreads();
        #pragma unroll
        for (int k8 = 0; k8 < 16; k8 += 8) {
            unsigned afr[2][4], bfr[2][2];
            #pragma unroll
            for (int mt = 0; mt < 2; mt++) {
                int mb = wm + mt * 16;
                afr[mt][0] = As[k8 + lt][mb + lg];
                afr[mt][1] = As[k8 + lt][mb + 8 + lg];
                afr[mt][2] = As[k8 + lt + 4][mb + lg];
                afr[mt][3] = As[k8 + lt + 4][mb + 8 + lg];
            }
            #pragma unroll
            for (int nt = 0; nt < 2; nt++) {
                bfr[nt][0] = Bs[k8 + lt][wn + nt * 8 + lg];
                bfr[nt][1] = Bs[k8 + lt + 4][wn + nt * 8 + lg];
            }
            #pragma unroll
            for (int mt = 0; mt < 2; mt++)
                #pragma unroll
                for (int nt = 0; nt < 2; nt++)
                    mma_tf32(c[mt][nt], afr[mt], bfr[nt][0], bfr[nt][1]);
        }
        __syncthreads();
    }

    #pragma unroll
    for (int mt = 0; mt < 2; mt++) {
        int r0 = m0 + wm + mt * 16 + lg;
        int l0 = r0 & 63, l8 = (r0 + 8) & 63;
        int s0 = snake_src(l0) * kD, s8 = snake_src(l8) * kD;
        #pragma unroll
        for (int nt = 0; nt < 2; nt++) {
            int gn = n0 + wn + nt * 8 + 2 * lt;
            C[(long)r0 * kD + gn]           = c[mt][nt][0] + pb[gn] + pos[s0 + gn];
            C[(long)r0 * kD + gn + 1]       = c[mt][nt][1] + pb[gn + 1] + pos[s0 + gn + 1];
            C[(long)(r0 + 8) * kD + gn]     = c[mt][nt][2] + pb[gn] + pos[s8 + gn];
            C[(long)(r0 + 8) * kD + gn + 1] = c[mt][nt][3] + pb[gn + 1] + pos[s8 + gn + 1];
        }
    }
}

// ---- TF32 GEMM, cp.async double-buffered, K-step 32, templated M-tile ----
template<int MT>
__global__ void __launch_bounds__(256) k_gemm_tc(
        const float* __restrict__ Abase,
        const float* __restrict__ B0, const float* __restrict__ B1,
        float* __restrict__ Cbase,
        int M, int N, int K, long sA, long sC) {
    extern __shared__ float smem[];
    constexpr int NTF = (MT == 128) ? 4 : 2;
    constexpr int ASTAGE = MT * kAStride;
    constexpr int BBASE = 2 * ASTAGE;
    int z = blockIdx.z;
    const float* A = Abase + (long)z * sA;
    const float* B = z ? B1 : B0;
    float* C = Cbase + (long)z * sC;
    int tid = threadIdx.x;
    int lane = tid & 31, warp = tid >> 5;
    int lg = lane >> 2, lt = lane & 3;
    int wm = (MT == 128) ? (warp >> 1) * 32 : (warp >> 2) * 32;
    int wn = (MT == 128) ? (warp & 1) * 32 : (warp & 3) * 16;
    int m0 = blockIdx.y * MT, n0 = blockIdx.x * 64;

    float c[2][NTF][4];
    #pragma unroll
    for (int a = 0; a < 2; a++)
        #pragma unroll
        for (int b = 0; b < NTF; b++)
            #pragma unroll
            for (int d = 0; d < 4; d++) c[a][b][d] = 0.f;

    int am = (MT == 128) ? (tid >> 1) : (tid >> 2);
    int ak = (MT == 128) ? (tid & 1) * 16 : (tid & 3) * 8;
    int bk = tid >> 3, bn = (tid & 7) * 8;

    if (n0 + 64 > N) {
        for (int i = tid; i < 2 * kBStage; i += 256) smem[BBASE + i] = 0.f;
        __syncthreads();
    }

    int nIters = K >> 5;

    {
        const float* ap = A + (long)(m0 + am) * K + ak;
        float* ad = &smem[am * kAStride + ak];
        cpa16(ad, ap); cpa16(ad + 4, ap + 4);
        if (MT == 128) { cpa16(ad + 8, ap + 8); cpa16(ad + 12, ap + 12); }
        const float* bp = B + (long)bk * N + n0 + bn;
        float* bd = &smem[BBASE + bk * kBStride + bn];
        if (n0 + bn < N) cpa16(bd, bp);
        if (n0 + bn + 4 < N) cpa16(bd + 4, bp + 4);
        asm volatile("cp.async.commit_group;");
    }

    for (int it = 0; it < nIters; it++) {
        if (it + 1 < nIters) {
            int k0 = (it + 1) << 5;
            int st = (it + 1) & 1;
            const float* ap = A + (long)(m0 + am) * K + k0 + ak;
            float* ad = &smem[st * ASTAGE + am * kAStride + ak];
            cpa16(ad, ap); cpa16(ad + 4, ap + 4);
            if (MT == 128) { cpa16(ad + 8, ap + 8); cpa16(ad + 12, ap + 12); }
            const float* bp = B + (long)(k0 + bk) * N + n0 + bn;
            float* bd = &smem[BBASE + st * kBStage + bk * kBStride + bn];
            if (n0 + bn < N) cpa16(bd, bp);
            if (n0 + bn + 4 < N) cpa16(bd + 4, bp + 4);
            asm volatile("cp.async.commit_group;");
            asm volatile("cp.async.wait_group 1;");
        } else {
            asm volatile("cp.async.wait_group 0;");
        }
        __syncthreads();

        const float* Ab = &smem[(it & 1) * ASTAGE];
        const float* Bb = &smem[BBASE + (it & 1) * kBStage];
        #pragma unroll
        for (int k8 = 0; k8 < 32; k8 += 8) {
            unsigned afr[2][4], bfr[NTF][2];
            #pragma unroll
            for (int mt = 0; mt < 2; mt++) {
                int mb = wm + mt * 16;
                afr[mt][0] = f2tf32(Ab[(mb + lg) * kAStride + k8 + lt]);
                afr[mt][1] = f2tf32(Ab[(mb + 8 + lg) * kAStride + k8 + lt]);
                afr[mt][2] = f2tf32(Ab[(mb + lg) * kAStride + k8 + lt + 4]);
                afr[mt][3] = f2tf32(Ab[(mb + 8 + lg) * kAStride + k8 + lt + 4]);
            }
            #pragma unroll
            for (int nt = 0; nt < NTF; nt++) {
                bfr[nt][0] = f2tf32(Bb[(k8 + lt) * kBStride + wn + nt * 8 + lg]);
                bfr[nt][1] = f2tf32(Bb[(k8 + lt + 4) * kBStride + wn + nt * 8 + lg]);
            }
            #pragma unroll
            for (int mt = 0; mt < 2; mt++)
                #pragma unroll
                for (int nt = 0; nt < NTF; nt++)
                    mma_tf32(c[mt][nt], afr[mt], bfr[nt][0], bfr[nt][1]);
        }
        __syncthreads();
    }

    #pragma unroll
    for (int mt = 0; mt < 2; mt++) {
        int r0 = m0 + wm + mt * 16 + lg;
        #pragma unroll
        for (int nt = 0; nt < NTF; nt++) {
            int gn = n0 + wn + nt * 8 + 2 * lt;
            if (gn < N) {
                C[(long)r0 * N + gn] = c[mt][nt][0];
                C[(long)(r0 + 8) * N + gn] = c[mt][nt][2];
                if (gn + 1 < N) {
                    C[(long)r0 * N + gn + 1] = c[mt][nt][1];
                    C[(long)(r0 + 8) * N + gn + 1] = c[mt][nt][3];
                }
            }
        }
    }
}

// ---- fused residual + rmsnorm ----
__global__ void k_resnorm(float* __restrict__ t, const float* __restrict__ o0,
                          const float* __restrict__ o1, const float* __restrict__ w,
                          float* __restrict__ nx, int addRes) {
    int row = blockIdx.x;
    int d = threadIdx.x;
    long i = (long)row * kD + d;
    float v = t[i];
    if (addRes) {
        v += 0.5f * (o0[i] + o1[i]);
        t[i] = v;
    }
    float ss = block_reduce_sum_256(v * v);
    nx[i] = v * rsqrtf(ss * (1.f / kD) + kEPS) * w[d];
}

// ---- dual-form scan on tensor cores: conv + dt + (G=C·Bᵀ, mask, Y=W·X) ----
// grid (kB, kH, 2), 512 threads (16 warps = 4m x 4n of 16x16 tiles).
__global__ void __launch_bounds__(512) k_attn(
        const float* __restrict__ zxbase,
        const float* __restrict__ cw0, const float* __restrict__ cw1,
        const float* __restrict__ cb0, const float* __restrict__ cb1,
        const float* __restrict__ dtb0, const float* __restrict__ dtb1,
        const float* __restrict__ Alog0, const float* __restrict__ Alog1,
        const float* __restrict__ Dp0, const float* __restrict__ Dp1,
        float* __restrict__ ybase) {
    extern __shared__ float sm[];
    int b = blockIdx.x, h = blockIdx.y, dir = blockIdx.z;
    const float* zx = zxbase + (long)dir * kTOK * kP;
    float* y        = ybase  + (long)dir * kTOK * kDIN;
    const float* cw  = dir ? cw1 : cw0;
    const float* cb  = dir ? cb1 : cb0;
    float a = -expf((dir ? Alog1 : Alog0)[h]);
    float dpar = (dir ? Dp1 : Dp0)[h];
    float dtbv = (dir ? dtb1 : dtb0)[h];
    int tid = threadIdx.x;
    int nthr = blockDim.x;   // 512

    // ---- phase 0: conv + silu.  seg0: X -> aXT transposed [p][s'];
    //      seg1: B -> aBm [s'][n]; seg2: C -> aCm [s][n].
    #pragma unroll
    for (int seg = 0; seg < 3; seg++) {
        int off = (seg == 0) ? h * kDH : (seg == 1) ? kDIN : kDIN + kN;
        for (int idx = tid; idx < 1024; idx += nthr) {
            int s = idx >> 4, q = (idx & 15) * 4;
            int tok = dir ? (kL - 1 - s) : s;
            float4 v = *(const float4*)&zx[(long)(b * kL + tok) * kP + kDIN + off + q];
            *(float4*)&sm[aST + s * 68 + q] = v;
        }
        __syncthreads();
        if (seg == 0) {
            // transposed write: aXT[p][s]
            for (int idx = tid; idx < 4096; idx += nthr) {
                int s = idx & 63, cc = idx >> 6;
                float acc = cb[off + cc];
                #pragma unroll
                for (int k = 0; k < 4; k++) {
                    int sp = s - 3 + k;
                    if (sp >= 0) acc += cw[(off + cc) * 4 + k] * sm[aST + sp * 68 + cc];
                }
                sm[aXT + cc * 68 + s] = siluf(acc);
            }
        } else {
            int dst = (seg == 1) ? aBm : aCm;
            for (int idx = tid; idx < 4096; idx += nthr) {
                int s = idx >> 6, cc = idx & 63;
                float acc = cb[off + cc];
                #pragma unroll
                for (int k = 0; k < 4; k++) {
                    int sp = s - 3 + k;
                    if (sp >= 0) acc += cw[(off + cc) * 4 + k] * sm[aST + sp * 68 + cc];
                }
                sm[dst + s * 68 + cc] = siluf(acc);
            }
        }
        __syncthreads();
    }

    // dt (softplus) + inclusive cumsum
    if (tid < 64) {
        int s = tid;
        int tok = dir ? (kL - 1 - s) : s;
        float v = zx[(long)(b * kL + tok) * kP + 2 * kDIN + 2 * kN + h] + dtbv;
        sm[aDT + s] = (v > 20.f) ? v : log1pf(expf(v));
    }
    __syncthreads();
    if (tid < 32) {
        float d0 = sm[aDT + 2 * tid], d1 = sm[aDT + 2 * tid + 1];
        float p = d0 + d1;
        #pragma unroll
        for (int o = 1; o < 32; o <<= 1) {
            float t = __shfl_up_sync(0xffffffffu, p, o);
            if (tid >= o) p += t;
        }
        sm[aCUM + 2 * tid] = p - d1;
        sm[aCUM + 2 * tid + 1] = p;
    }
    __syncthreads();

    int warp = tid >> 5, lane = tid & 31;
    int lg = lane >> 2, lt = lane & 3;
    int mw = (warp >> 2) * 16;       // s rows
    int nw = (warp & 3) * 16;        // sp / p cols

    // ---- phase 1: G = C @ B^T via tf32 MMA ----
    float g[2][4];
    #pragma unroll
    for (int nt = 0; nt < 2; nt++)
        #pragma unroll
        for (int d = 0; d < 4; d++) g[nt][d] = 0.f;
    #pragma unroll
    for (int k0 = 0; k0 < 64; k0 += 8) {
        unsigned af[4];
        af[0] = f2tf32(sm[aCm + (mw + lg) * 68 + k0 + lt]);
        af[1] = f2tf32(sm[aCm + (mw + 8 + lg) * 68 + k0 + lt]);
        af[2] = f2tf32(sm[aCm + (mw + lg) * 68 + k0 + lt + 4]);
        af[3] = f2tf32(sm[aCm + (mw + 8 + lg) * 68 + k0 + lt + 4]);
        #pragma unroll
        for (int nt = 0; nt < 2; nt++) {
            unsigned b0 = f2tf32(sm[aBm + (nw + nt * 8 + lg) * 68 + k0 + lt]);
            unsigned b1 = f2tf32(sm[aBm + (nw + nt * 8 + lg) * 68 + k0 + lt + 4]);
            mma_tf32(g[nt], af, b0, b1);
        }
    }
    __syncthreads();   // all C/B reads done; aCm can be overwritten with W

    // mask + store W into aCm [s][sp]
    {
        int s0 = mw + lg, s8 = mw + 8 + lg;
        float cum0 = sm[aCUM + s0], cum8 = sm[aCUM + s8];
        #pragma unroll
        for (int nt = 0; nt < 2; nt++) {
            int sp = nw + nt * 8 + 2 * lt;
            float csp0 = sm[aCUM + sp], csp1 = sm[aCUM + sp + 1];
            float dt0 = sm[aDT + sp], dt1 = sm[aDT + sp + 1];
            sm[aCm + s0 * 68 + sp]     = (sp     <= s0) ? g[nt][0] * __expf(a * (cum0 - csp0)) * dt0 : 0.f;
            sm[aCm + s0 * 68 + sp + 1] = (sp + 1 <= s0) ? g[nt][1] * __expf(a * (cum0 - csp1)) * dt1 : 0.f;
            sm[aCm + s8 * 68 + sp]     = (sp     <= s8) ? g[nt][2] * __expf(a * (cum8 - csp0)) * dt0 : 0.f;
            sm[aCm + s8 * 68 + sp + 1] = (sp + 1 <= s8) ? g[nt][3] * __expf(a * (cum8 - csp1)) * dt1 : 0.f;
        }
    }
    __syncthreads();

    // ---- phase 2: Y = W @ X via tf32 MMA (A = W[s][sp], B-op = XT[p][sp]) ----
    float yv[2][4];
    #pragma unroll
    for (int nt = 0; nt < 2; nt++)
        #pragma unroll
        for (int d = 0; d < 4; d++) yv[nt][d] = 0.f;
    #pragma unroll
    for (int k0 = 0; k0 < 64; k0 += 8) {
        unsigned af[4];
        af[0] = f2tf32(sm[aCm + (mw + lg) * 68 + k0 + lt]);
        af[1] = f2tf32(sm[aCm + (mw + 8 + lg) * 68 + k0 + lt]);
        af[2] = f2tf32(sm[aCm + (mw + lg) * 68 + k0 + lt + 4]);
        af[3] = f2tf32(sm[aCm + (mw + 8 + lg) * 68 + k0 + lt + 4]);
        #pragma unroll
        for (int nt = 0; nt < 2; nt++) {
            unsigned b0 = f2tf32(sm[aXT + (nw + nt * 8 + lg) * 68 + k0 + lt]);
            unsigned b1 = f2tf32(sm[aXT + (nw + nt * 8 + lg) * 68 + k0 + lt + 4]);
            mma_tf32(yv[nt], af, b0, b1);
        }
    }

    // epilogue: + D*x, write token-order (float2 pairs)
    {
        int s0 = mw + lg, s8 = mw + 8 + lg;
        int tok0 = dir ? (kL - 1 - s0) : s0;
        int tok8 = dir ? (kL - 1 - s8) : s8;
        #pragma unroll
        for (int nt = 0; nt < 2; nt++) {
            int p0 = nw + nt * 8 + 2 * lt;
            float x00 = sm[aXT + p0 * 68 + s0];
            float x01 = sm[aXT + (p0 + 1) * 68 + s0];
            float x80 = sm[aXT + p0 * 68 + s8];
            float x81 = sm[aXT + (p0 + 1) * 68 + s8];
            float2 o0 = make_float2(yv[nt][0] + dpar * x00, yv[nt][1] + dpar * x01);
            float2 o8 = make_float2(yv[nt][2] + dpar * x80, yv[nt][3] + dpar * x81);
            *(float2*)&y[(long)(b * kL + tok0) * kDIN + h * kDH + p0] = o0;
            *(float2*)&y[(long)(b * kL + tok8) * kDIN + h * kDH + p0] = o8;
        }
    }
}

// ---- gate + rmsnorm over DIN, both dirs ----
__global__ void k_gate_norm2(const float* __restrict__ zxbase,
                             const float* __restrict__ gn0, const float* __restrict__ gn1,
                             float* __restrict__ ybase) {
    int row = blockIdx.x;
    const float* gn = (row >= kTOK) ? gn1 : gn0;
    const float* zrow = zxbase + (long)row * kP;
    float* yrow = ybase + (long)row * kDIN;
    int t = threadIdx.x;
    float v0 = yrow[t] * siluf(zrow[t]);
    float v1 = yrow[t + 256] * siluf(zrow[t + 256]);
    float ss = block_reduce_sum_256(v0 * v0 + v1 * v1);
    float sc = rsqrtf(ss * (1.f / kDIN) + kEPS);
    yrow[t]       = v0 * sc * gn[t];
    yrow[t + 256] = v1 * sc * gn[t + 256];
}

// ---- fused mean-pool + classifier head; grid (kB, 5), 200 classes/block ----
__global__ void k_meanhead(const float* __restrict__ nx, const float* __restrict__ hw,
                           const float* __restrict__ hb, float* __restrict__ out) {
    int b = blockIdx.x;
    int c0 = blockIdx.y * 200;
    int t = threadIdx.x;
    __shared__ float pool[kD];
    float s = 0.f;
    #pragma unroll 8
    for (int l = 0; l < kL; l++) s += nx[(long)(b * kL + l) * kD + t];
    pool[t] = s * (1.f / kL);
    __syncthreads();
    for (int n = c0 + t; n < c0 + 200 && n < kCLS; n += 256) {
        float acc = hb[n];
        #pragma unroll 8
        for (int k = 0; k < kD; k++) acc += pool[k] * hw[(long)k * kCLS + n];
        out[(long)b * kCLS + n] = acc;
    }
}

// ---------------- launch ----------------
extern "C" void kernel_launch(void* const* d_in, const int* in_sizes, int n_in,
                              void* d_out, int out_size) {
    const float* x       = (const float*)d_in[0];
    const float* patch_w = (const float*)d_in[1];
    const float* patch_b = (const float*)d_in[2];
    const float* pos     = (const float*)d_in[3];
    const float* norms_w = (const float*)d_in[4];
    const float* final_w = (const float*)d_in[5];
    const float* head_w  = (const float*)d_in[6];
    const float* head_b  = (const float*)d_in[7];
    const float* Win[2]  = {(const float*)d_in[8],  (const float*)d_in[16]};
    const float* cw[2]   = {(const float*)d_in[9],  (const float*)d_in[17]};
    const float* cb[2]   = {(const float*)d_in[10], (const float*)d_in[18]};
    const float* dtb[2]  = {(const float*)d_in[11], (const float*)d_in[19]};
    const float* Alog[2] = {(const float*)d_in[12], (const float*)d_in[20]};
    const float* Dp[2]   = {(const float*)d_in[13], (const float*)d_in[21]};
    const float* gn[2]   = {(const float*)d_in[14], (const float*)d_in[22]};
    const float* Wout[2] = {(const float*)d_in[15], (const float*)d_in[23]};
    float* out = (float*)d_out;

    float *p_t, *p_nx, *p_zx, *p_y, *p_o;
    cudaGetSymbolAddress((void**)&p_t, g_t);
    cudaGetSymbolAddress((void**)&p_nx, g_nx);
    cudaGetSymbolAddress((void**)&p_zx, g_zx);
    cudaGetSymbolAddress((void**)&p_y, g_y);
    cudaGetSymbolAddress((void**)&p_o, g_o);

    const int smem64  = (2 * 64 * kAStride + 2 * kBStage) * 4;
    cudaFuncSetAttribute(k_gemm_tc<64>,  cudaFuncAttributeMaxDynamicSharedMemorySize, smem64);
    cudaFuncSetAttribute(k_attn, cudaFuncAttributeMaxDynamicSharedMemorySize, kAttnSmemBytes);

    // stem: fused patchify + GEMM + bias + pos
    {
        dim3 g(kD / 64, kTOK / 64);
        k_gemm_patch<<<g, 256>>>(x, patch_w, patch_b, pos, p_t);
    }

    for (int i = 0; i < 2; i++) {
        if (i == 0)
            k_resnorm<<<kTOK, 256>>>(p_t, p_o, p_o, norms_w, p_nx, 0);
        else
            k_resnorm<<<kTOK, 256>>>(p_t, p_o, p_o + kTOK * kD, norms_w + kD, p_nx, 1);
        {
            dim3 g((kP + 63) / 64, kTOK / 64, 2);
            k_gemm_tc<64><<<g, 256, smem64>>>(p_nx, Win[0] + i * kD * kP, Win[1] + i * kD * kP,
                                              p_zx, kTOK, kP, kD, 0, (long)kTOK * kP);
        }
        {
            dim3 g(kB, kH, 2);
            k_attn<<<g, 512, kAttnSmemBytes>>>(p_zx,
                                    cw[0] + i * kCDIM * 4, cw[1] + i * kCDIM * 4,
                                    cb[0] + i * kCDIM, cb[1] + i * kCDIM,
                                    dtb[0] + i * kH, dtb[1] + i * kH,
                                    Alog[0] + i * kH, Alog[1] + i * kH,
                                    Dp[0] + i * kH, Dp[1] + i * kH, p_y);
        }
        k_gate_norm2<<<2 * kTOK, 256>>>(p_zx, gn[0] + i * kDIN, gn[1] + i * kDIN, p_y);
        {
            dim3 g(kD / 64, kTOK / 64, 2);
            k_gemm_tc<64><<<g, 256, smem64>>>(p_y, Wout[0] + i * kDIN * kD, Wout[1] + i * kDIN * kD,
                                              p_o, kTOK, kD, kDIN, (long)kTOK * kDIN, (long)kTOK * kD);
        }
    }

    // final residual + norm, then fused mean+head
    k_resnorm<<<kTOK, 256>>>(p_t, p_o, p_o + kTOK * kD, final_w, p_nx, 1);
    k_meanhead<<<dim3(kB, 5), 256>>>(p_nx, head_w, head_b, out);
}